// round 2
// baseline (speedup 1.0000x reference)
#include <cuda_runtime.h>

namespace {
constexpr int kB = 16;
constexpr int kT = 4096;
constexpr int kD = 512;
constexpr int kChunk = 32;            // time steps per chunk
constexpr int kCB = kChunk * kB;      // 512 rows per chunk
constexpr int kNC = kT / kChunk;      // 128 chunks
constexpr int kDD = kD * kD;
constexpr float kLR = 0.01f;
}

// Time-major projections: row r = t*kB + b
__device__ float g_q[(size_t)kB * kT * kD];
__device__ float g_k[(size_t)kB * kT * kD];
__device__ float g_v[(size_t)kB * kT * kD];
__device__ float g_G[(size_t)kNC * kDD];            // per-chunk Gram (LR * V^T K)
__device__ float g_S[(size_t)kNC * kDD];            // exclusive prefix state per chunk
__device__ float g_A[(size_t)kNC * kCB * kCB];      // masked intra-chunk scores

__device__ __forceinline__ void scatter4(float (&S)[16][64], int k4, int col, float4 v) {
    S[k4 + 0][col] = v.x;
    S[k4 + 1][col] = v.y;
    S[k4 + 2][col] = v.z;
    S[k4 + 3][col] = v.w;
}

__device__ __forceinline__ void mma_tile(const float (&As)[16][64], const float (&Bs)[16][64],
                                         float (&acc)[4][4], int ty, int tx) {
#pragma unroll
    for (int kk = 0; kk < 16; kk++) {
        float4 a = *(const float4*)&As[kk][ty * 4];
        float4 b = *(const float4*)&Bs[kk][tx * 4];
        float av[4] = {a.x, a.y, a.z, a.w};
        float bv[4] = {b.x, b.y, b.z, b.w};
#pragma unroll
        for (int i = 0; i < 4; i++)
#pragma unroll
            for (int j = 0; j < 4; j++) acc[i][j] += av[i] * bv[j];
    }
}

// q/k/v = x @ W^T, written time-major. Grid (1536/64 cols, 65536/64 rows).
__global__ void proj_kernel(const float* __restrict__ x, const float* __restrict__ Wq,
                            const float* __restrict__ Wk, const float* __restrict__ Wv) {
    __shared__ float As[16][64], Bs[16][64];
    int tid = threadIdx.x;
    int tx = tid & 15, ty = tid >> 4;
    int r0 = blockIdx.y * 64;
    int c0 = blockIdx.x * 64;
    int sel = c0 / kD;
    const float* W = (sel == 0) ? Wq : (sel == 1 ? Wk : Wv);
    float* dst = (sel == 0) ? g_q : (sel == 1 ? g_k : g_v);
    int e0 = c0 - sel * kD;

    int l_col = tid >> 2;          // 0..63
    int l_k4 = (tid & 3) << 2;     // 0,4,8,12
    int gr = r0 + l_col;
    int t = gr >> 4, b = gr & 15;  // r = t*16 + b
    const float* xrow = x + ((size_t)b * kT + t) * kD;
    const float* wrow = W + (size_t)(e0 + l_col) * kD;

    float acc[4][4] = {};
    for (int k0 = 0; k0 < kD; k0 += 16) {
        scatter4(As, l_k4, l_col, *(const float4*)(xrow + k0 + l_k4));
        scatter4(Bs, l_k4, l_col, *(const float4*)(wrow + k0 + l_k4));
        __syncthreads();
        mma_tile(As, Bs, acc, ty, tx);
        __syncthreads();
    }
#pragma unroll
    for (int i = 0; i < 4; i++) {
        int r = r0 + ty * 4 + i;
        *(float4*)(dst + (size_t)r * kD + e0 + tx * 4) =
            make_float4(acc[i][0], acc[i][1], acc[i][2], acc[i][3]);
    }
}

// G_c[d][e] = LR * sum_{r in chunk} v[r][d] * k[r][e]
__global__ void gram_kernel() {
    __shared__ float As[16][64], Bs[16][64];
    int tid = threadIdx.x, tx = tid & 15, ty = tid >> 4;
    int c = blockIdx.z, m0 = blockIdx.y * 64, n0 = blockIdx.x * 64;
    int base = c * kCB;
    int l_kk = tid >> 4;            // 0..15
    int l_c4 = (tid & 15) << 2;     // 0..60
    float acc[4][4] = {};
    for (int k0 = 0; k0 < kCB; k0 += 16) {
        const float* vrow = g_v + (size_t)(base + k0 + l_kk) * kD;
        const float* krow = g_k + (size_t)(base + k0 + l_kk) * kD;
        *(float4*)&As[l_kk][l_c4] = *(const float4*)(vrow + m0 + l_c4);
        *(float4*)&Bs[l_kk][l_c4] = *(const float4*)(krow + n0 + l_c4);
        __syncthreads();
        mma_tile(As, Bs, acc, ty, tx);
        __syncthreads();
    }
#pragma unroll
    for (int i = 0; i < 4; i++) {
        int m = m0 + ty * 4 + i;
        *(float4*)(g_G + (size_t)c * kDD + (size_t)m * kD + n0 + tx * 4) =
            make_float4(kLR * acc[i][0], kLR * acc[i][1], kLR * acc[i][2], kLR * acc[i][3]);
    }
}

// S_c = memory0 + sum_{c' < c} G_{c'}  (exclusive prefix). Only sequential stage.
__global__ void prefix_kernel(const float* __restrict__ mem0) {
    int idx = blockIdx.x * blockDim.x + threadIdx.x;
    float acc = mem0[idx];
    for (int c = 0; c < kNC; c++) {
        g_S[(size_t)c * kDD + idx] = acc;
        acc += g_G[(size_t)c * kDD + idx];
    }
}

// A_c[i][j] = (t_j <= t_i) ? LR * (q_i . k_j) : 0   (block-causal, diag blocks included)
__global__ void scores_kernel() {
    __shared__ float As[16][64], Bs[16][64];
    int tid = threadIdx.x, tx = tid & 15, ty = tid >> 4;
    int c = blockIdx.z, i0 = blockIdx.y * 64, j0 = blockIdx.x * 64;
    int base = c * kCB;
    int l_col = tid >> 2, l_k4 = (tid & 3) << 2;
    const float* qrow = g_q + (size_t)(base + i0 + l_col) * kD;
    const float* krow = g_k + (size_t)(base + j0 + l_col) * kD;
    float acc[4][4] = {};
    for (int k0 = 0; k0 < kD; k0 += 16) {
        scatter4(As, l_k4, l_col, *(const float4*)(qrow + k0 + l_k4));
        scatter4(Bs, l_k4, l_col, *(const float4*)(krow + k0 + l_k4));
        __syncthreads();
        mma_tile(As, Bs, acc, ty, tx);
        __syncthreads();
    }
    int tj = (j0 + tx * 4) >> 4;  // 4 consecutive cols share one time block (B=16)
#pragma unroll
    for (int i = 0; i < 4; i++) {
        int li = i0 + ty * 4 + i;
        int ti = li >> 4;
        float m = (tj <= ti) ? kLR : 0.0f;
        *(float4*)(g_A + (size_t)c * kCB * kCB + (size_t)li * kCB + j0 + tx * 4) =
            make_float4(m * acc[i][0], m * acc[i][1], m * acc[i][2], m * acc[i][3]);
    }
}

// out = A_c @ V_c + Q_c @ S_c^T, written back in [B,T,D] layout.
__global__ void out_kernel(float* __restrict__ out) {
    __shared__ float As[16][64], Bs[16][64];
    int tid = threadIdx.x, tx = tid & 15, ty = tid >> 4;
    int c = blockIdx.z, i0 = blockIdx.y * 64, d0 = blockIdx.x * 64;
    int base = c * kCB;
    int l_col = tid >> 2, l_k4 = (tid & 3) << 2;
    int l_kk = tid >> 4, l_c4 = (tid & 15) << 2;
    float acc[4][4] = {};

    // phase 1: intra = A @ V  (K = kCB)
    const float* arow = g_A + (size_t)c * kCB * kCB + (size_t)(i0 + l_col) * kCB;
    for (int k0 = 0; k0 < kCB; k0 += 16) {
        scatter4(As, l_k4, l_col, *(const float4*)(arow + k0 + l_k4));
        *(float4*)&Bs[l_kk][l_c4] =
            *(const float4*)(g_v + (size_t)(base + k0 + l_kk) * kD + d0 + l_c4);
        __syncthreads();
        mma_tile(As, Bs, acc, ty, tx);
        __syncthreads();
    }
    // phase 2: inter = Q @ S^T  (K = kD); Bs[e][d] = S[d][e]
    const float* qrow = g_q + (size_t)(base + i0 + l_col) * kD;
    const float* srow = g_S + (size_t)c * kDD + (size_t)(d0 + l_col) * kD;
    for (int e0 = 0; e0 < kD; e0 += 16) {
        scatter4(As, l_k4, l_col, *(const float4*)(qrow + e0 + l_k4));
        scatter4(Bs, l_k4, l_col, *(const float4*)(srow + e0 + l_k4));
        __syncthreads();
        mma_tile(As, Bs, acc, ty, tx);
        __syncthreads();
    }
#pragma unroll
    for (int i = 0; i < 4; i++) {
        int li = i0 + ty * 4 + i;
        int tc = li >> 4, b = li & 15;
        int t = c * kChunk + tc;
        *(float4*)(out + ((size_t)b * kT + t) * kD + d0 + tx * 4) =
            make_float4(acc[i][0], acc[i][1], acc[i][2], acc[i][3]);
    }
}

extern "C" void kernel_launch(void* const* d_in, const int* in_sizes, int n_in,
                              void* d_out, int out_size) {
    const float* x = (const float*)d_in[0];
    const float* Wq = (const float*)d_in[1];
    const float* Wk = (const float*)d_in[2];
    const float* Wv = (const float*)d_in[3];
    const float* mem0 = (const float*)d_in[4];
    float* out = (float*)d_out;

    proj_kernel<<<dim3(3 * kD / 64, (kB * kT) / 64), 256>>>(x, Wq, Wk, Wv);
    gram_kernel<<<dim3(kD / 64, kD / 64, kNC), 256>>>();
    prefix_kernel<<<kDD / 256, 256>>>(mem0);
    scores_kernel<<<dim3(kCB / 64, kCB / 64, kNC), 256>>>();
    out_kernel<<<dim3(kD / 64, kCB / 64, kNC), 256>>>(out);
}

// round 10
// speedup vs baseline: 2.7947x; 2.7947x over previous
#include <cuda_runtime.h>
#include <cuda_fp16.h>
#include <cstdint>

namespace {
constexpr int kB = 16, kT = 4096, kD = 512;
constexpr int kChunk = 32;            // time steps per chunk
constexpr int kCB = kChunk * kB;      // 512 rows per chunk
constexpr int kNC = kT / kChunk;      // 128 chunks
constexpr int kN = kB * kT;           // 65536 total rows
constexpr size_t kDD = (size_t)kD * kD;
constexpr float kLR = 0.01f;
constexpr int kPadH = 40;                 // halfs per smem row (32 data + 8 pad) -> conflict-free
constexpr int kTileH = 128 * kPadH;       // 5120 halfs = 10240 B per plane tile
constexpr int kDynSmem = 2 * 4 * kTileH * 2;  // 2 buffers x (AH,AL,BH,BL) = 81920 B
}

// hi/lo fp16 split planes (x ~= hi + lo; lo = rn(x - hi))
__device__ __half g_xh[(size_t)kN * kD], g_xl[(size_t)kN * kD];
__device__ __half g_wh[3 * kDD], g_wl[3 * kDD];
__device__ __half g_qh[(size_t)kN * kD], g_ql[(size_t)kN * kD];
__device__ __half g_kh[(size_t)kN * kD], g_kl[(size_t)kN * kD];
__device__ __half g_vh[(size_t)kN * kD], g_vl[(size_t)kN * kD];
__device__ __half g_kth[(size_t)kD * kN], g_ktl[(size_t)kD * kN];  // transposed copies
__device__ __half g_vth[(size_t)kD * kN], g_vtl[(size_t)kD * kN];
__device__ __half g_Ah[(size_t)kNC * kCB * kCB], g_Al[(size_t)kNC * kCB * kCB];
__device__ __half g_Sh[(size_t)kNC * kDD], g_Sl[(size_t)kNC * kDD];
__device__ float g_G[(size_t)kNC * kDD];  // per-chunk Gram (fp32, prefix input)

// ---------------- helpers ----------------
__device__ __forceinline__ void cp16(uint32_t saddr, const void* gptr) {
    asm volatile("cp.async.cg.shared.global [%0], [%1], 16;" :: "r"(saddr), "l"(gptr));
}
__device__ __forceinline__ void cp_commit() { asm volatile("cp.async.commit_group;" ::: "memory"); }
template <int N>
__device__ __forceinline__ void cp_wait() { asm volatile("cp.async.wait_group %0;" :: "n"(N) : "memory"); }

__device__ __forceinline__ void mma_f16(float (&d)[4], const uint32_t (&a)[4], const uint32_t (&b)[2]) {
    asm volatile(
        "mma.sync.aligned.m16n8k16.row.col.f32.f16.f16.f32 "
        "{%0,%1,%2,%3}, {%4,%5,%6,%7}, {%8,%9}, {%0,%1,%2,%3};"
        : "+f"(d[0]), "+f"(d[1]), "+f"(d[2]), "+f"(d[3])
        : "r"(a[0]), "r"(a[1]), "r"(a[2]), "r"(a[3]), "r"(b[0]), "r"(b[1]));
}

// split one fp32 into (hi, lo) halves
__device__ __forceinline__ void split2(float v, __half& h, __half& l) {
    h = __float2half_rn(v);
    l = __float2half_rn(v - __half2float(h));
}

// ---------------- shared GEMM: C[128,128] = A[128,K] @ B[128,K]^T ----------------
// 256 threads, 8 warps (2 x 4), warp tile 64x32, K in chunks of 32 halfs.
// aRow/bRow(row, k0, lo) -> pointer to 32 contiguous halfs of that operand plane.
// store2(row, col, v0, v1) sinks C pairs (col, col+1).
template <int NCHUNK, typename FA, typename FB, typename FS>
__device__ __forceinline__ void gemm_mma(FA aRow, FB bRow, FS store2) {
    extern __shared__ __half smh[];
    const int tid = threadIdx.x, lane = tid & 31, w = tid >> 5;
    const int wm = (w & 1) * 64, wn = (w >> 1) * 32;
    const int g = lane >> 2, t4 = lane & 3;

    float acc[4][4][4] = {};

    auto load = [&](int it) {
        int p = it & 1, k0 = it * 32;
        uint32_t sb = (uint32_t)__cvta_generic_to_shared(smh + (size_t)p * 4 * kTileH);
#pragma unroll
        for (int i = 0; i < 2; i++) {
            int slot = tid + 256 * i;              // 512 slots: 4 x 16B per row
            int row = slot >> 2, c8 = (slot & 3) * 8;
            uint32_t soff = (uint32_t)(row * kPadH + c8) * 2;
            cp16(sb + soff, aRow(row, k0, 0) + c8);
            cp16(sb + (uint32_t)kTileH * 2 + soff, aRow(row, k0, 1) + c8);
            cp16(sb + (uint32_t)kTileH * 4 + soff, bRow(row, k0, 0) + c8);
            cp16(sb + (uint32_t)kTileH * 6 + soff, bRow(row, k0, 1) + c8);
        }
        cp_commit();
    };

    load(0);
    for (int it = 0; it < NCHUNK; ++it) {
        if (it + 1 < NCHUNK) { load(it + 1); cp_wait<1>(); }
        else                 { cp_wait<0>(); }
        __syncthreads();
        const __half* AH = smh + (size_t)(it & 1) * 4 * kTileH;
        const __half* AL = AH + kTileH;
        const __half* BH = AH + 2 * kTileH;
        const __half* BL = AH + 3 * kTileH;
#pragma unroll
        for (int s = 0; s < 2; s++) {
            const int kk = s * 16 + 2 * t4;
            uint32_t aH[4][4], aL[4][4], bH[4][2], bL[4][2];
#pragma unroll
            for (int mt = 0; mt < 4; mt++) {
                int ro = (wm + mt * 16 + g) * kPadH + kk;
                aH[mt][0] = *(const uint32_t*)(AH + ro);
                aH[mt][1] = *(const uint32_t*)(AH + ro + 8 * kPadH);
                aH[mt][2] = *(const uint32_t*)(AH + ro + 8);
                aH[mt][3] = *(const uint32_t*)(AH + ro + 8 * kPadH + 8);
                aL[mt][0] = *(const uint32_t*)(AL + ro);
                aL[mt][1] = *(const uint32_t*)(AL + ro + 8 * kPadH);
                aL[mt][2] = *(const uint32_t*)(AL + ro + 8);
                aL[mt][3] = *(const uint32_t*)(AL + ro + 8 * kPadH + 8);
            }
#pragma unroll
            for (int nt = 0; nt < 4; nt++) {
                int ro = (wn + nt * 8 + g) * kPadH + kk;
                bH[nt][0] = *(const uint32_t*)(BH + ro);
                bH[nt][1] = *(const uint32_t*)(BH + ro + 8);
                bL[nt][0] = *(const uint32_t*)(BL + ro);
                bL[nt][1] = *(const uint32_t*)(BL + ro + 8);
            }
#pragma unroll
            for (int mt = 0; mt < 4; mt++)
#pragma unroll
                for (int nt = 0; nt < 4; nt++) {
                    mma_f16(acc[mt][nt], aH[mt], bH[nt]);   // hi*hi
                    mma_f16(acc[mt][nt], aH[mt], bL[nt]);   // hi*lo
                    mma_f16(acc[mt][nt], aL[mt], bH[nt]);   // lo*hi
                }
        }
        __syncthreads();
    }

#pragma unroll
    for (int mt = 0; mt < 4; mt++)
#pragma unroll
        for (int nt = 0; nt < 4; nt++)
#pragma unroll
            for (int h = 0; h < 2; h++)
                store2(wm + mt * 16 + g + h * 8, wn + nt * 8 + t4 * 2,
                       acc[mt][nt][h * 2], acc[mt][nt][h * 2 + 1]);
}

// ---------------- stage kernels ----------------
__global__ void split_kernel(const float* __restrict__ src, __half* __restrict__ hi,
                             __half* __restrict__ lo, int n) {
    int i = blockIdx.x * blockDim.x + threadIdx.x;
    if (i < n) split2(src[i], hi[i], lo[i]);
}

// q/k/v = x @ W^T (time-major rows), plus transposed copies k_t, v_t. All split-form.
__global__ void proj_kernel() {
    int m0 = blockIdx.y * 128, n0 = blockIdx.x * 128;
    int sel = n0 >> 9, e0 = n0 & 511;
    const __half* WH = g_wh + (size_t)sel * kDD;
    const __half* WL = g_wl + (size_t)sel * kDD;
    __half* dstH = (sel == 0) ? g_qh : (sel == 1 ? g_kh : g_vh);
    __half* dstL = (sel == 0) ? g_ql : (sel == 1 ? g_kl : g_vl);
    __half* dstTH = (sel == 1) ? g_kth : (sel == 2 ? g_vth : nullptr);
    __half* dstTL = (sel == 1) ? g_ktl : (sel == 2 ? g_vtl : nullptr);

    auto aRow = [&](int row, int k0, int lo) -> const __half* {
        int r = m0 + row;
        const __half* base = lo ? g_xl : g_xh;
        return base + ((size_t)(r & 15) * kT + (r >> 4)) * kD + k0;
    };
    auto bRow = [&](int row, int k0, int lo) -> const __half* {
        return (lo ? WL : WH) + (size_t)(e0 + row) * kD + k0;
    };
    auto store2 = [&](int row, int col, float v0, float v1) {
        int r = m0 + row, e = e0 + col;
        __half h0, l0, h1, l1;
        split2(v0, h0, l0); split2(v1, h1, l1);
        *(__half2*)(dstH + (size_t)r * kD + e) = __halves2half2(h0, h1);
        *(__half2*)(dstL + (size_t)r * kD + e) = __halves2half2(l0, l1);
        if (dstTH) {
            dstTH[(size_t)e * kN + r] = h0; dstTH[(size_t)(e + 1) * kN + r] = h1;
            dstTL[(size_t)e * kN + r] = l0; dstTL[(size_t)(e + 1) * kN + r] = l1;
        }
    };
    gemm_mma<16>(aRow, bRow, store2);
}

// G_c = LR * V_c^T K_c  (fp32 output; prefix input)
__global__ void gram_kernel() {
    int c = blockIdx.z;
    size_t rbase = (size_t)c * kCB;
    int m0 = blockIdx.y * 128, n0 = blockIdx.x * 128;
    auto aRow = [&](int row, int k0, int lo) -> const __half* {
        return (lo ? g_vtl : g_vth) + (size_t)(m0 + row) * kN + rbase + k0;
    };
    auto bRow = [&](int row, int k0, int lo) -> const __half* {
        return (lo ? g_ktl : g_kth) + (size_t)(n0 + row) * kN + rbase + k0;
    };
    float* dst = g_G + (size_t)c * kDD;
    auto store2 = [&](int row, int col, float v0, float v1) {
        *(float2*)(dst + (size_t)(m0 + row) * kD + n0 + col) = make_float2(kLR * v0, kLR * v1);
    };
    gemm_mma<16>(aRow, bRow, store2);
}

// S_c = memory0 + sum_{c'<c} G_{c'}  (exclusive prefix; only sequential stage) -> split planes
__global__ void prefix_kernel(const float* __restrict__ mem0) {
    int idx = blockIdx.x * blockDim.x + threadIdx.x;
    float acc = mem0[idx];
    for (int c = 0; c < kNC; c++) {
        __half h, l;
        split2(acc, h, l);
        g_Sh[(size_t)c * kDD + idx] = h;
        g_Sl[(size_t)c * kDD + idx] = l;
        acc += g_G[(size_t)c * kDD + idx];
    }
}

// A_c[i][j] = (t_j <= t_i) ? LR * (q_i . k_j) : 0   (block-causal, diag included) -> split planes
__global__ void scores_kernel() {
    int c = blockIdx.z;
    size_t base = (size_t)c * kCB;
    int i0 = blockIdx.y * 128, j0 = blockIdx.x * 128;
    auto aRow = [&](int row, int k0, int lo) -> const __half* {
        return (lo ? g_ql : g_qh) + (base + i0 + row) * kD + k0;
    };
    auto bRow = [&](int row, int k0, int lo) -> const __half* {
        return (lo ? g_kl : g_kh) + (base + j0 + row) * kD + k0;
    };
    auto store2 = [&](int row, int col, float v0, float v1) {
        int li = i0 + row, lj = j0 + col;  // lj even: lj, lj+1 share a 16-block
        float m = ((lj >> 4) <= (li >> 4)) ? kLR : 0.0f;
        __half h0, l0, h1, l1;
        split2(m * v0, h0, l0); split2(m * v1, h1, l1);
        size_t off = (size_t)c * kCB * kCB + (size_t)li * kCB + lj;
        *(__half2*)(g_Ah + off) = __halves2half2(h0, h1);
        *(__half2*)(g_Al + off) = __halves2half2(l0, l1);
    };
    gemm_mma<16>(aRow, bRow, store2);
}

// out = A_c @ V_c + Q_c @ S_c^T  (single accumulator: chunks 0-15 intra, 16-31 inter)
__global__ void out_kernel(float* __restrict__ out) {
    int c = blockIdx.z;
    size_t base = (size_t)c * kCB;
    int i0 = blockIdx.y * 128, d0 = blockIdx.x * 128;
    auto aRow = [&](int row, int k0, int lo) -> const __half* {
        if (k0 < kCB)
            return (lo ? g_Al : g_Ah) + (size_t)c * kCB * kCB + (size_t)(i0 + row) * kCB + k0;
        return (lo ? g_ql : g_qh) + (base + i0 + row) * kD + (k0 - kCB);
    };
    auto bRow = [&](int row, int k0, int lo) -> const __half* {
        if (k0 < kCB)
            return (lo ? g_vtl : g_vth) + (size_t)(d0 + row) * kN + base + k0;
        return (lo ? g_Sl : g_Sh) + (size_t)c * kDD + (size_t)(d0 + row) * kD + (k0 - kCB);
    };
    auto store2 = [&](int row, int col, float v0, float v1) {
        int li = i0 + row;
        int t = c * kChunk + (li >> 4), b = li & 15;
        *(float2*)(out + ((size_t)b * kT + t) * kD + d0 + col) = make_float2(v0, v1);
    };
    gemm_mma<32>(aRow, bRow, store2);
}

extern "C" void kernel_launch(void* const* d_in, const int* in_sizes, int n_in,
                              void* d_out, int out_size) {
    const float* x = (const float*)d_in[0];
    const float* Wq = (const float*)d_in[1];
    const float* Wk = (const float*)d_in[2];
    const float* Wv = (const float*)d_in[3];
    const float* mem0 = (const float*)d_in[4];
    float* out = (float*)d_out;

    cudaFuncSetAttribute(proj_kernel, cudaFuncAttributeMaxDynamicSharedMemorySize, kDynSmem);
    cudaFuncSetAttribute(gram_kernel, cudaFuncAttributeMaxDynamicSharedMemorySize, kDynSmem);
    cudaFuncSetAttribute(scores_kernel, cudaFuncAttributeMaxDynamicSharedMemorySize, kDynSmem);
    cudaFuncSetAttribute(out_kernel, cudaFuncAttributeMaxDynamicSharedMemorySize, kDynSmem);

    __half *p_xh, *p_xl, *p_wh, *p_wl;
    cudaGetSymbolAddress((void**)&p_xh, g_xh);
    cudaGetSymbolAddress((void**)&p_xl, g_xl);
    cudaGetSymbolAddress((void**)&p_wh, g_wh);
    cudaGetSymbolAddress((void**)&p_wl, g_wl);

    const int nx = kN * kD;
    split_kernel<<<nx / 256, 256>>>(x, p_xh, p_xl, nx);
    split_kernel<<<(int)(kDD / 256), 256>>>(Wq, p_wh, p_wl, (int)kDD);
    split_kernel<<<(int)(kDD / 256), 256>>>(Wk, p_wh + kDD, p_wl + kDD, (int)kDD);
    split_kernel<<<(int)(kDD / 256), 256>>>(Wv, p_wh + 2 * kDD, p_wl + 2 * kDD, (int)kDD);

    proj_kernel<<<dim3(12, kN / 128), 256, kDynSmem>>>();
    gram_kernel<<<dim3(4, 4, kNC), 256, kDynSmem>>>();
    prefix_kernel<<<(int)(kDD / 256), 256>>>(mem0);
    scores_kernel<<<dim3(4, 4, kNC), 256, kDynSmem>>>();
    out_kernel<<<dim3(4, 4, kNC), 256, kDynSmem>>>(out);
}